// round 1
// baseline (speedup 1.0000x reference)
#include <cuda_runtime.h>

// Problem constants (fixed by reference: x is (16,3,512,512), PATCH=16, STRIDE=8, k=8)
#define BB     16
#define CC     3
#define HH     512
#define WW     512
#define PSZ    16
#define STR    8
#define NH     63
#define NW     63
#define NN     (NH * NW)          // 3969
#define FDIM   (CC * PSZ * PSZ)   // 768
#define KNB    8
#define F4PER  (FDIM / 4)         // 192 float4 per patch row

// ---------------------------------------------------------------------------
// Kernel 1: patches. One thread = one float4 of the (B, N, 768) output.
// f = c*256 + u*16 + v  ->  float4 index r = c*64 + u*4 + vg  (vg = v/4)
// value = x[b, c, i*8+u, j*8+vg*4 .. +3], which is a 16B-aligned float4.
// Consecutive threads write consecutive output float4s (perfect coalescing)
// and read consecutive 16B input chunks within a row.
// ---------------------------------------------------------------------------
__global__ void __launch_bounds__(256)
patches_kernel(const float* __restrict__ x, float* __restrict__ out)
{
    int tid = blockIdx.x * blockDim.x + threadIdx.x;   // < B*N*192 = 12,192,768
    if (tid >= BB * NN * F4PER) return;

    int r  = tid % F4PER;        // 0..191
    int bn = tid / F4PER;
    int n  = bn % NN;
    int b  = bn / NN;

    int c  = r >> 6;             // r / 64
    int u  = (r >> 2) & 15;      // (r % 64) / 4
    int vg = r & 3;              // v / 4

    int i = n / NW;
    int j = n % NW;

    const float4* src = reinterpret_cast<const float4*>(
        x + (((b * CC + c) * HH + (i * STR + u)) * WW + j * STR)) + vg;

    reinterpret_cast<float4*>(out)[tid] = __ldg(src);
}

// ---------------------------------------------------------------------------
// Kernel 2: positions + edge_index. One thread per (b, n).
// kNN on the regular grid: the 8 nearest (after self) are always within
// Chebyshev radius 2. Key = d2*4096 + idx reproduces top_k's ordering
// (d2 ascending, index ascending on ties) in a single int compare.
// Output layout (after patches): positions (B,N,2) then edge_index (B,2,N*8),
// all as float32 (indices are < 4096, exactly representable).
// ---------------------------------------------------------------------------
__global__ void __launch_bounds__(256)
pos_edge_kernel(float* __restrict__ out)
{
    int t = blockIdx.x * blockDim.x + threadIdx.x;     // < B*N = 63504
    if (t >= BB * NN) return;

    int n = t % NN;
    int b = t / NN;
    int i = n / NW;
    int j = n % NW;

    const long long P0 = (long long)BB * NN * FDIM;          // positions base
    const long long E0 = P0 + (long long)BB * NN * 2;        // edge base

    // positions[b, n] = (i, j)
    out[P0 + (long long)t * 2 + 0] = (float)i;
    out[P0 + (long long)t * 2 + 1] = (float)j;

    // gather candidates in radius-2 window
    int keys[24];
    int cnt = 0;
    #pragma unroll
    for (int di = -2; di <= 2; di++) {
        #pragma unroll
        for (int dj = -2; dj <= 2; dj++) {
            if (di == 0 && dj == 0) continue;
            int ii = i + di;
            int jj = j + dj;
            if (ii < 0 || ii >= NH || jj < 0 || jj >= NW) continue;
            int d2 = di * di + dj * dj;                 // <= 8 < 4096/...
            keys[cnt++] = d2 * 4096 + (ii * NW + jj);   // idx < 3969 < 4096
        }
    }
    // cnt >= 8 always (corner: exactly 8)

    long long ebase = E0 + (long long)b * 2 * NN * KNB;
    float fn = (float)n;

    #pragma unroll
    for (int m = 0; m < KNB; m++) {
        int best = 0;
        for (int q = 1; q < cnt; q++)
            if (keys[q] < keys[best]) best = q;
        int idx = keys[best] & 4095;
        keys[best] = 0x7fffffff;
        // src row then tgt row of edge_index (shape (2, N*8) per batch)
        out[ebase + (long long)n * KNB + m] = fn;
        out[ebase + (long long)NN * KNB + (long long)n * KNB + m] = (float)idx;
    }
}

// ---------------------------------------------------------------------------
extern "C" void kernel_launch(void* const* d_in, const int* in_sizes, int n_in,
                              void* d_out, int out_size)
{
    const float* x = (const float*)d_in[0];
    float* out = (float*)d_out;

    int total_f4 = BB * NN * F4PER;                    // 12,192,768
    patches_kernel<<<(total_f4 + 255) / 256, 256>>>(x, out);

    int total_bn = BB * NN;                            // 63,504
    pos_edge_kernel<<<(total_bn + 255) / 256, 256>>>(out);
}

// round 2
// speedup vs baseline: 1.2992x; 1.2992x over previous
#include <cuda_runtime.h>

#define BB     16
#define CC     3
#define HH     512
#define WW     512
#define PSZ    16
#define STR    8
#define NH     63
#define NW     63
#define NN     (NH * NW)          // 3969
#define FDIM   (CC * PSZ * PSZ)   // 768
#define KNB    8
#define F4PER  (FDIM / 4)         // 192 float4 per patch row

#define PATCH_F4     (BB * NN * F4PER)             // 12,192,768
#define PATCH_BLOCKS (PATCH_F4 / 256)              // 47,628 (exact)
#define POS_FLOATS   (BB * NN * 2)                 // 127,008
#define EDGE_FLOATS  (BB * 2 * NN * KNB)           // 1,016,064
#define EXTRA_FLOATS (POS_FLOATS + EDGE_FLOATS)    // 1,143,072
#define EXTRA_BLOCKS ((EXTRA_FLOATS + 255) / 256)  // 4,466

// Per-n neighbor indices (identical across batch). 3969*8 ints = 127 KB.
__device__ int g_nbr[NN * KNB];

// ---------------------------------------------------------------------------
// Kernel A: compute 8 nearest neighbors per grid node (one thread per n).
// Candidates = Chebyshev radius-2 window (24 max); key = d2*4096 + idx
// reproduces top_k(-d2) ordering (d2 asc, idx asc). Top-8 kept in a sorted
// 8-register list via a fully-unrolled compare-exchange insertion chain —
// no dynamic register indexing, so no local-memory spill.
// ---------------------------------------------------------------------------
#define CX(a, b) { int _lo = min(a, b); b = max(a, b); a = _lo; }

__global__ void __launch_bounds__(256)
nbr_kernel()
{
    int n = blockIdx.x * blockDim.x + threadIdx.x;
    if (n >= NN) return;
    int i = n / NW;
    int j = n % NW;

    int t0 = 0x7fffffff, t1 = 0x7fffffff, t2 = 0x7fffffff, t3 = 0x7fffffff;
    int t4 = 0x7fffffff, t5 = 0x7fffffff, t6 = 0x7fffffff, t7 = 0x7fffffff;

    #pragma unroll
    for (int di = -2; di <= 2; di++) {
        #pragma unroll
        for (int dj = -2; dj <= 2; dj++) {
            if (di == 0 && dj == 0) continue;
            int ii = i + di;
            int jj = j + dj;
            bool ok = (ii >= 0) & (ii < NH) & (jj >= 0) & (jj < NW);
            int key = ok ? ((di*di + dj*dj) * 4096 + (ii * NW + jj))
                         : 0x7fffffff;
            // single bubble pass inserts key into the sorted list t0..t7
            int t8 = key;
            CX(t7, t8); CX(t6, t7); CX(t5, t6); CX(t4, t5);
            CX(t3, t4); CX(t2, t3); CX(t1, t2); CX(t0, t1);
        }
    }

    int* dst = g_nbr + n * KNB;
    dst[0] = t0 & 4095; dst[1] = t1 & 4095; dst[2] = t2 & 4095; dst[3] = t3 & 4095;
    dst[4] = t4 & 4095; dst[5] = t5 & 4095; dst[6] = t6 & 4095; dst[7] = t7 & 4095;
}

// ---------------------------------------------------------------------------
// Kernel B (fused): blocks [0, EXTRA_BLOCKS) write positions + edge_index
// (one thread per float, fully coalesced); remaining blocks do the patch
// gather, one float4 per thread.
// ---------------------------------------------------------------------------
__global__ void __launch_bounds__(256)
fused_kernel(const float* __restrict__ x, float* __restrict__ out)
{
    int bid = blockIdx.x;

    if (bid < EXTRA_BLOCKS) {
        int e = bid * 256 + threadIdx.x;
        if (e >= EXTRA_FLOATS) return;

        const long long P0 = (long long)BB * NN * FDIM;
        if (e < POS_FLOATS) {
            int n = (e >> 1) % NN;
            int v = (e & 1) ? (n % NW) : (n / NW);
            out[P0 + e] = (float)v;
        } else {
            int e2 = e - POS_FLOATS;             // < 1,016,064
            int r  = e2 % (2 * NN * KNB);        // within-batch offset
            float v;
            if (r < NN * KNB) {
                v = (float)(r >> 3);             // src row: node id
            } else {
                v = (float)g_nbr[r - NN * KNB];  // tgt row: neighbor id
            }
            out[P0 + POS_FLOATS + e2] = v;
        }
        return;
    }

    // ---- patch gather ----
    int tid = (bid - EXTRA_BLOCKS) * 256 + threadIdx.x;   // < PATCH_F4 exactly

    int r  = tid % F4PER;
    int bn = tid / F4PER;
    int n  = bn % NN;
    int b  = bn / NN;

    int c  = r >> 6;
    int u  = (r >> 2) & 15;
    int vg = r & 3;

    int i = n / NW;
    int j = n % NW;

    const float4* src = reinterpret_cast<const float4*>(
        x + (((b * CC + c) * HH + (i * STR + u)) * WW + j * STR)) + vg;

    float4 val = __ldg(src);
    __stcs(reinterpret_cast<float4*>(out) + tid, val);   // streaming store
}

// ---------------------------------------------------------------------------
extern "C" void kernel_launch(void* const* d_in, const int* in_sizes, int n_in,
                              void* d_out, int out_size)
{
    const float* x = (const float*)d_in[0];
    float* out = (float*)d_out;

    nbr_kernel<<<(NN + 255) / 256, 256>>>();
    fused_kernel<<<EXTRA_BLOCKS + PATCH_BLOCKS, 256>>>(x, out);
}

// round 3
// speedup vs baseline: 1.6209x; 1.2476x over previous
#include <cuda_runtime.h>

#define BB     16
#define CC     3
#define HH     512
#define WW     512
#define PSZ    16
#define STR    8
#define NH     63
#define NW     63
#define NN     (NH * NW)          // 3969
#define FDIM   (CC * PSZ * PSZ)   // 768
#define KNB    8
#define F4PER  (FDIM / 4)         // 192

#define PATCH_F4      (BB * NN * F4PER)             // 12,192,768
#define PATCH_BLOCKS4 (PATCH_F4 / 1024)             // 11,907 (exact)
#define POS_FLOATS    (BB * NN * 2)                 // 127,008
#define EDGE_FLOATS   (BB * 2 * NN * KNB)           // 1,016,064
#define EXTRA_FLOATS  (POS_FLOATS + EDGE_FLOATS)    // 1,143,072
#define EXTRA_BLOCKS  ((EXTRA_FLOATS + 255) / 256)  // 4,466

#define CX(a, b) { int _lo = min(a, b); b = max(a, b); a = _lo; }

// ---------------------------------------------------------------------------
// Single fused kernel.
//  blocks [0, EXTRA_BLOCKS):   positions + edge_index, one float per thread,
//                              coalesced. Edge targets compute their own kNN
//                              in registers (sorted insertion network over the
//                              Chebyshev radius-2 window; key = d2*4096 + idx
//                              reproduces top_k(-d2)'s (d2 asc, idx asc)
//                              ordering) — ~0.4us aggregate ALU, fully
//                              overlapped with the memory-bound gather.
//  blocks [EXTRA_BLOCKS, ...): patch gather, 4 block-strided float4s per
//                              thread (4 independent LDG.128 in flight).
// ---------------------------------------------------------------------------
__global__ void __launch_bounds__(256)
fused_kernel(const float* __restrict__ x, float* __restrict__ out)
{
    int bid = blockIdx.x;

    if (bid < EXTRA_BLOCKS) {
        int e = bid * 256 + threadIdx.x;
        if (e >= EXTRA_FLOATS) return;

        const long long P0 = (long long)BB * NN * FDIM;

        if (e < POS_FLOATS) {
            int n = (e >> 1) % NN;
            out[P0 + e] = (float)((e & 1) ? (n % NW) : (n / NW));
            return;
        }

        int e2 = e - POS_FLOATS;              // < 1,016,064
        int r  = e2 % (2 * NN * KNB);         // within-batch offset in (2, N*8)
        float v;
        if (r < NN * KNB) {
            v = (float)(r >> 3);              // src row: node id
        } else {
            int q = r - NN * KNB;
            int n = q >> 3;
            int m = q & 7;
            int i = n / NW;
            int j = n % NW;

            int t0 = 0x7fffffff, t1 = 0x7fffffff, t2 = 0x7fffffff, t3 = 0x7fffffff;
            int t4 = 0x7fffffff, t5 = 0x7fffffff, t6 = 0x7fffffff, t7 = 0x7fffffff;
            #pragma unroll
            for (int di = -2; di <= 2; di++) {
                #pragma unroll
                for (int dj = -2; dj <= 2; dj++) {
                    if (di == 0 && dj == 0) continue;
                    int ii = i + di;
                    int jj = j + dj;
                    bool ok = (ii >= 0) & (ii < NH) & (jj >= 0) & (jj < NW);
                    int key = ok ? ((di*di + dj*dj) * 4096 + (ii * NW + jj))
                                 : 0x7fffffff;
                    int t8 = key;
                    CX(t7, t8); CX(t6, t7); CX(t5, t6); CX(t4, t5);
                    CX(t3, t4); CX(t2, t3); CX(t1, t2); CX(t0, t1);
                }
            }
            // static mux tree on m (no dynamic register indexing)
            int a0 = (m & 1) ? t1 : t0;
            int a1 = (m & 1) ? t3 : t2;
            int a2 = (m & 1) ? t5 : t4;
            int a3 = (m & 1) ? t7 : t6;
            int b0 = (m & 2) ? a1 : a0;
            int b1 = (m & 2) ? a3 : a2;
            int sel = (m & 4) ? b1 : b0;
            v = (float)(sel & 4095);
        }
        out[P0 + POS_FLOATS + e2] = v;
        return;
    }

    // ---- patch gather: 4 block-strided float4s per thread ----
    int base = (bid - EXTRA_BLOCKS) * 1024 + threadIdx.x;

    float4 val[4];
    #pragma unroll
    for (int k = 0; k < 4; k++) {
        int tid = base + k * 256;             // < PATCH_F4 exactly (11,907*1024)

        int r  = tid % F4PER;
        int bn = tid / F4PER;
        int n  = bn % NN;
        int b  = bn / NN;

        int c  = r >> 6;
        int u  = (r >> 2) & 15;
        int vg = r & 3;

        int i = n / NW;
        int j = n % NW;

        const float4* src = reinterpret_cast<const float4*>(
            x + (((b * CC + c) * HH + (i * STR + u)) * WW + j * STR)) + vg;
        val[k] = __ldg(src);
    }

    #pragma unroll
    for (int k = 0; k < 4; k++)
        __stcs(reinterpret_cast<float4*>(out) + base + k * 256, val[k]);
}

// ---------------------------------------------------------------------------
extern "C" void kernel_launch(void* const* d_in, const int* in_sizes, int n_in,
                              void* d_out, int out_size)
{
    const float* x = (const float*)d_in[0];
    float* out = (float*)d_out;

    fused_kernel<<<EXTRA_BLOCKS + PATCH_BLOCKS4, 256>>>(x, out);
}